// round 15
// baseline (speedup 1.0000x reference)
#include <cuda_runtime.h>
#include <cuda_fp16.h>
#include <cstdint>

#define NMAX   100352
#define BUCKET 128                 // per-node CSR capacity (Poisson(32) tail safe)
#define C_IN   300
#define C1     64
#define HEADS  4
#define OUT2   32
#define SLOPE  0.2f

// ---------------- device scratch (zero-initialized at module load) ----------------
__device__ __align__(16) __half g_hh[(size_t)NMAX * C1];    // x@W1 fp16     [N,64]
__device__ __align__(16) float  g_x1[(size_t)NMAX * C1];    // relu(GAT)+b1  [N,64]
__device__ __align__(16) float2 g_eas[(size_t)NMAX * HEADS];// (exp(as), exp(.2as))
__device__ __align__(16) float  g_ad[(size_t)NMAX * HEADS];
__device__ __align__(16) __half g_h2s[(size_t)NMAX * OUT2]; // dinv*(x1@W2)  [N,32] fp16
__device__ __align__(16) float  g_dinv[NMAX];
__device__ int g_dega[NMAX], g_degb[NMAX];   // start 0; gathers re-clear after use
__device__ __align__(16) int g_csra[(size_t)NMAX * BUCKET];
__device__ __align__(16) int g_csrb[(size_t)NMAX * BUCKET];
__device__ int g_is64_a, g_is64_b;

__device__ __forceinline__ float leaky(float v) { return v > 0.f ? v : SLOPE * v; }

__device__ __forceinline__ uint64_t pack2(float lo, float hi) {
    uint64_t r; asm("mov.b64 %0,{%1,%2};" : "=l"(r) : "f"(lo), "f"(hi)); return r;
}
__device__ __forceinline__ float2 unpack2(uint64_t v) {
    float2 f; asm("mov.b64 {%0,%1},%2;" : "=f"(f.x), "=f"(f.y) : "l"(v)); return f;
}
__device__ __forceinline__ void ffma2(uint64_t& d, uint64_t a, uint64_t b) {
    asm("fma.rn.f32x2 %0, %1, %2, %0;" : "+l"(d) : "l"(a), "l"(b));
}

// ---------------- K0: detect edge dtype ----------------
__global__ void k_detect(const int* __restrict__ a, const int* __restrict__ b) {
    __shared__ int sa, sb;
    if (threadIdx.x == 0) { sa = 0; sb = 0; }
    __syncthreads();
    atomicOr(&sa, a[2 * threadIdx.x + 1]);
    atomicOr(&sb, b[2 * threadIdx.x + 1]);
    __syncthreads();
    if (threadIdx.x == 0) {
        g_is64_a = (sa == 0) ? 1 : 0;
        g_is64_b = (sb == 0) ? 1 : 0;
    }
}

// ---------------- K1: h = x @ W1 (f32x2) + fused attn reduction ----------
#define KT 64
__global__ void k_gemm1(const float* __restrict__ x,
                        const float* __restrict__ W1,
                        const float* __restrict__ att_src,
                        const float* __restrict__ att_dst, int N) {
    __shared__ float xs[KT][68];
    __shared__ float Ws[KT][64];
    const int tid = threadIdx.x;
    const int nb  = blockIdx.x * 64;
    const int n0  = (tid >> 4) * 4;
    const int c0  = (tid & 15) * 4;

    uint64_t acc[4][2];
#pragma unroll
    for (int i = 0; i < 4; i++) { acc[i][0] = pack2(0.f, 0.f); acc[i][1] = pack2(0.f, 0.f); }

    for (int j0 = 0; j0 < C_IN; j0 += KT) {
#pragma unroll
        for (int k = 0; k < (64 * KT) / 256; k++) {
            int idx = tid + k * 256;
            int n = idx / KT, j = idx % KT;
            int nn = nb + n;
            float v = 0.f;
            if ((j0 + j) < C_IN && nn < N) v = x[(size_t)nn * C_IN + j0 + j];
            xs[j][n] = v;
        }
#pragma unroll
        for (int k = 0; k < (64 * KT) / 256; k++) {
            int idx = tid + k * 256;
            int j = idx >> 6, c = idx & 63;
            float v = 0.f;
            if ((j0 + j) < C_IN) v = W1[(size_t)(j0 + j) * 64 + c];
            Ws[j][c] = v;
        }
        __syncthreads();
#pragma unroll
        for (int j = 0; j < KT; j++) {
            float4 a = *(const float4*)&xs[j][n0];
            uint64_t b0 = *(const uint64_t*)&Ws[j][c0];
            uint64_t b1 = *(const uint64_t*)&Ws[j][c0 + 2];
            uint64_t ax = pack2(a.x, a.x), ay = pack2(a.y, a.y);
            uint64_t az = pack2(a.z, a.z), aw = pack2(a.w, a.w);
            ffma2(acc[0][0], ax, b0); ffma2(acc[0][1], ax, b1);
            ffma2(acc[1][0], ay, b0); ffma2(acc[1][1], ay, b1);
            ffma2(acc[2][0], az, b0); ffma2(acc[2][1], az, b1);
            ffma2(acc[3][0], aw, b0); ffma2(acc[3][1], aw, b1);
        }
        __syncthreads();
    }

    float4 us = *(const float4*)&att_src[c0];
    float4 ud = *(const float4*)&att_dst[c0];
    int lane = tid & 31;
    int head = (lane & 15) >> 2;

    float pas[4], pad[4];
#pragma unroll
    for (int i = 0; i < 4; i++) {
        float2 lo = unpack2(acc[i][0]), hi = unpack2(acc[i][1]);
        int n = nb + n0 + i;
        if (n < N) {
            __half2 h2a = __floats2half2_rn(lo.x, lo.y);
            __half2 h2b = __floats2half2_rn(hi.x, hi.y);
            uint2 pk;
            pk.x = *(uint32_t*)&h2a;
            pk.y = *(uint32_t*)&h2b;
            *(uint2*)&g_hh[(size_t)n * C1 + c0] = pk;
        }
        pas[i] = lo.x * us.x + lo.y * us.y + hi.x * us.z + hi.y * us.w;
        pad[i] = lo.x * ud.x + lo.y * ud.y + hi.x * ud.z + hi.y * ud.w;
    }
#pragma unroll
    for (int off = 1; off <= 2; off <<= 1) {
#pragma unroll
        for (int i = 0; i < 4; i++) {
            pas[i] += __shfl_xor_sync(0xffffffffu, pas[i], off);
            pad[i] += __shfl_xor_sync(0xffffffffu, pad[i], off);
        }
    }
    if ((lane & 3) == 0) {
#pragma unroll
        for (int i = 0; i < 4; i++) {
            int n = nb + n0 + i;
            if (n < N) {
                g_eas[(size_t)n * 4 + head] =
                    make_float2(__expf(pas[i]), __expf(SLOPE * pas[i]));
                g_ad[(size_t)n * 4 + head] = pad[i];
            }
        }
    }
}

// ---------------- single-pass bucket CSR scatter ----------------
__global__ void k_scatter(const int* __restrict__ ei, long long E, const int* flag,
                          int* __restrict__ deg, int* __restrict__ csr) {
    long long e = (long long)blockIdx.x * blockDim.x + threadIdx.x;
    if (e >= E) return;
    int src, dst;
    if (*flag) {
        src = (int)((const long long*)ei)[e];
        dst = (int)((const long long*)ei)[E + e];
    } else {
        src = ei[(size_t)e];
        dst = ei[(size_t)(E + e)];
    }
    int pos = atomicAdd(&deg[dst], 1);
    if (pos < BUCKET) csr[((size_t)dst << 7) + pos] = src;
}

// ---------------- GAT gather: warp per dst, prefetched int4 CSR ----------
// w_e = (exp(as) > exp(-ad)) ? exp(as)*exp(ad) : exp(.2as)*exp(.2ad)
__global__ void k_gat_gather(const float* __restrict__ b1, int N) {
    int n = (blockIdx.x * blockDim.x + threadIdx.x) >> 5;
    int lane = threadIdx.x & 31;
    if (n >= N) return;
    int head = lane >> 3;
    float adv = g_ad[n * 4 + head];
    float ead  = __expf(adv);
    float ea2d = __expf(SLOPE * adv);
    float th   = __expf(-adv);
    // self loop
    float2 es = g_eas[(size_t)n * 4 + head];
    float w = (es.x > th) ? es.x * ead : es.y * ea2d;
    float2 hv = __half22float2(*(const __half2*)&g_hh[(size_t)n * C1 + lane * 2]);
    float den = w;
    float ax = w * hv.x, ay = w * hv.y;
    size_t roff = (size_t)n << 7;   // bucket base, 16B-aligned
    int deg = g_dega[n];
    if (deg > BUCKET) deg = BUCKET;
    if (lane == 0) g_dega[n] = 0;   // self-clear for next replay
    int j = 0;
    int4 nxt;
    if (deg >= 4) nxt = *(const int4*)&g_csra[roff];
    for (; j + 4 <= deg; j += 4) {
        int4 ss = nxt;
        if (j + 8 <= deg) nxt = *(const int4*)&g_csra[roff + j + 4];  // prefetch
        float2 h0 = __half22float2(*(const __half2*)&g_hh[(size_t)ss.x * C1 + lane * 2]);
        float2 h1 = __half22float2(*(const __half2*)&g_hh[(size_t)ss.y * C1 + lane * 2]);
        float2 h2 = __half22float2(*(const __half2*)&g_hh[(size_t)ss.z * C1 + lane * 2]);
        float2 h3 = __half22float2(*(const __half2*)&g_hh[(size_t)ss.w * C1 + lane * 2]);
        float2 e0 = g_eas[(size_t)ss.x * 4 + head];
        float2 e1 = g_eas[(size_t)ss.y * 4 + head];
        float2 e2 = g_eas[(size_t)ss.z * 4 + head];
        float2 e3 = g_eas[(size_t)ss.w * 4 + head];
        float w0 = (e0.x > th) ? e0.x * ead : e0.y * ea2d;
        float w1 = (e1.x > th) ? e1.x * ead : e1.y * ea2d;
        float w2 = (e2.x > th) ? e2.x * ead : e2.y * ea2d;
        float w3 = (e3.x > th) ? e3.x * ead : e3.y * ea2d;
        den += (w0 + w1) + (w2 + w3);
        ax += w0 * h0.x + w1 * h1.x + w2 * h2.x + w3 * h3.x;
        ay += w0 * h0.y + w1 * h1.y + w2 * h2.y + w3 * h3.y;
    }
    for (; j < deg; j++) {
        int s0 = g_csra[roff + j];
        float2 e0 = g_eas[(size_t)s0 * 4 + head];
        float w0 = (e0.x > th) ? e0.x * ead : e0.y * ea2d;
        float2 h0 = __half22float2(*(const __half2*)&g_hh[(size_t)s0 * C1 + lane * 2]);
        den += w0;
        ax += w0 * h0.x;
        ay += w0 * h0.y;
    }
    float r = 1.f / den;
    float2 bv = *(const float2*)&b1[lane * 2];
    float2 o;
    o.x = fmaxf(ax * r + bv.x, 0.f);
    o.y = fmaxf(ay * r + bv.y, 0.f);
    *(float2*)&g_x1[(size_t)n * C1 + lane * 2] = o;
}

// ---------------- GCN prep: h2s = dinv*(x1 @ W2) fp16, dinv ----------
__global__ void k_gcn_prep(const float* __restrict__ W2, int N) {
    __shared__ float Wsh[C1 * OUT2];
    int tid = threadIdx.x;
    for (int i = tid; i < C1 * OUT2; i += blockDim.x) Wsh[i] = W2[i];
    __syncthreads();
    int warp = tid >> 5, lane = tid & 31;
    int n = blockIdx.x * (blockDim.x >> 5) + warp;
    if (n >= N) return;
    float dv = rsqrtf((float)(g_degb[n] + 1));
    if (lane == 0) g_dinv[n] = dv;
    float acc = 0.f;
#pragma unroll
    for (int k = 0; k < C1; k++)
        acc += g_x1[(size_t)n * C1 + k] * Wsh[k * OUT2 + lane];
    g_h2s[(size_t)n * OUT2 + lane] = __float2half_rn(acc * dv);
}

// ---------------- GCN gather: warp per dst, prefetched int4 CSR, 8-edge body --
__global__ void k_gcn_gather(const float* __restrict__ b2,
                             float* __restrict__ out, int N) {
    int n = (blockIdx.x * blockDim.x + threadIdx.x) >> 5;
    int lane = threadIdx.x & 31;
    if (n >= N) return;
    float dv = g_dinv[n];
    float acc = __half2float(g_h2s[(size_t)n * OUT2 + lane]);  // self term
    size_t roff = (size_t)n << 7;
    int deg = g_degb[n];
    if (deg > BUCKET) deg = BUCKET;
    if (lane == 0) g_degb[n] = 0;   // self-clear for next replay
    int j = 0;
    int4 na, nb_;
    if (deg >= 8) {
        na  = *(const int4*)&g_csrb[roff];
        nb_ = *(const int4*)&g_csrb[roff + 4];
    }
    for (; j + 8 <= deg; j += 8) {
        int4 sa = na, sb = nb_;
        if (j + 16 <= deg) {                      // prefetch next iteration
            na  = *(const int4*)&g_csrb[roff + j + 8];
            nb_ = *(const int4*)&g_csrb[roff + j + 12];
        }
        float v0 = __half2float(g_h2s[(size_t)sa.x * OUT2 + lane]);
        float v1 = __half2float(g_h2s[(size_t)sa.y * OUT2 + lane]);
        float v2 = __half2float(g_h2s[(size_t)sa.z * OUT2 + lane]);
        float v3 = __half2float(g_h2s[(size_t)sa.w * OUT2 + lane]);
        float v4 = __half2float(g_h2s[(size_t)sb.x * OUT2 + lane]);
        float v5 = __half2float(g_h2s[(size_t)sb.y * OUT2 + lane]);
        float v6 = __half2float(g_h2s[(size_t)sb.z * OUT2 + lane]);
        float v7 = __half2float(g_h2s[(size_t)sb.w * OUT2 + lane]);
        acc += ((v0 + v1) + (v2 + v3)) + ((v4 + v5) + (v6 + v7));
    }
    for (; j + 4 <= deg; j += 4) {
        int4 sa = *(const int4*)&g_csrb[roff + j];
        acc += __half2float(g_h2s[(size_t)sa.x * OUT2 + lane])
             + __half2float(g_h2s[(size_t)sa.y * OUT2 + lane])
             + __half2float(g_h2s[(size_t)sa.z * OUT2 + lane])
             + __half2float(g_h2s[(size_t)sa.w * OUT2 + lane]);
    }
    for (; j < deg; j++) {
        int s0 = g_csrb[roff + j];
        acc += __half2float(g_h2s[(size_t)s0 * OUT2 + lane]);
    }
    out[(size_t)n * OUT2 + lane] = b2[lane] + dv * acc;
}

// ---------------- launch (forked-stream graph; static resources) ----------------
extern "C" void kernel_launch(void* const* d_in, const int* in_sizes, int n_in,
                              void* d_out, int out_size) {
    const float* x       = (const float*)d_in[0];
    const float* W1      = (const float*)d_in[1];
    const float* att_src = (const float*)d_in[2];
    const float* att_dst = (const float*)d_in[3];
    const float* b1      = (const float*)d_in[4];
    const float* W2      = (const float*)d_in[5];
    const float* b2      = (const float*)d_in[6];
    const int* ei        = (const int*)d_in[7];
    const int* sei       = (const int*)d_in[8];
    float* out = (float*)d_out;

    int N = in_sizes[0] / C_IN;
    long long E  = in_sizes[7] / 2;
    long long E2 = in_sizes[8] / 2;

    int *p_dega, *p_degb, *p_csra, *p_csrb, *p_fa, *p_fb;
    cudaGetSymbolAddress((void**)&p_dega, g_dega);
    cudaGetSymbolAddress((void**)&p_degb, g_degb);
    cudaGetSymbolAddress((void**)&p_csra, g_csra);
    cudaGetSymbolAddress((void**)&p_csrb, g_csrb);
    cudaGetSymbolAddress((void**)&p_fa, g_is64_a);
    cudaGetSymbolAddress((void**)&p_fb, g_is64_b);

    // created once on the correctness call; reused thereafter (no alloc in capture)
    static cudaStream_t s1 = nullptr, s2 = nullptr;
    static cudaEvent_t evF = nullptr, evA = nullptr, evB = nullptr;
    if (!s1) {
        cudaStreamCreateWithFlags(&s1, cudaStreamNonBlocking);
        cudaStreamCreateWithFlags(&s2, cudaStreamNonBlocking);
        cudaEventCreateWithFlags(&evF, cudaEventDisableTiming);
        cudaEventCreateWithFlags(&evA, cudaEventDisableTiming);
        cudaEventCreateWithFlags(&evB, cudaEventDisableTiming);
    }

    // detect on origin stream first (both CSR branches need the dtype flags)
    k_detect<<<1, 128>>>(ei, sei);
    cudaEventRecord(evF, 0);
    cudaStreamWaitEvent(s1, evF, 0);
    cudaStreamWaitEvent(s2, evF, 0);

    // branch S1: GAT bucket CSR (deg self-cleared by k_gat_gather)
    k_scatter<<<(unsigned)((E + 255) / 256), 256, 0, s1>>>(ei, E, p_fa, p_dega, p_csra);
    cudaEventRecord(evA, s1);

    // branch S2: GCN bucket CSR (deg self-cleared by k_gcn_gather)
    k_scatter<<<(unsigned)((E2 + 255) / 256), 256, 0, s2>>>(sei, E2, p_fb, p_degb, p_csrb);
    cudaEventRecord(evB, s2);

    // origin stream: dense compute with fused attention
    k_gemm1<<<(N + 63) / 64, 256>>>(x, W1, att_src, att_dst, N);

    cudaStreamWaitEvent(0, evA, 0);
    k_gat_gather<<<(N * 32 + 255) / 256, 256>>>(b1, N);
    cudaStreamWaitEvent(0, evB, 0);
    k_gcn_prep<<<(N + 7) / 8, 256>>>(W2, N);
    k_gcn_gather<<<(N * 32 + 255) / 256, 256>>>(b2, out, N);
}

// round 16
// speedup vs baseline: 1.4634x; 1.4634x over previous
#include <cuda_runtime.h>
#include <cuda_fp16.h>
#include <cstdint>

#define NMAX   100352
#define BUCKET 128                 // per-node CSR capacity (Poisson(32) tail safe)
#define C_IN   300
#define C1     64
#define HEADS  4
#define OUT2   32
#define SLOPE  0.2f

// ---------------- device scratch ----------------
__device__ __align__(16) __half g_hh[(size_t)NMAX * C1];    // x@W1 fp16     [N,64]
__device__ __align__(16) float  g_x1[(size_t)NMAX * C1];    // relu(GAT)+b1  [N,64]
__device__ __align__(16) float2 g_eas[(size_t)NMAX * HEADS];// (exp(as), exp(.2as))
__device__ __align__(16) float  g_ad[(size_t)NMAX * HEADS];
__device__ __align__(16) __half g_h2s[(size_t)NMAX * OUT2]; // dinv*(x1@W2)  [N,32] fp16
__device__ __align__(16) float  g_dinv[NMAX];
__device__ int g_dega[NMAX], g_degb[NMAX];
__device__ __align__(16) int g_csra[(size_t)NMAX * BUCKET];
__device__ __align__(16) int g_csrb[(size_t)NMAX * BUCKET];
__device__ int g_is64_a, g_is64_b;

__device__ __forceinline__ float leaky(float v) { return v > 0.f ? v : SLOPE * v; }

__device__ __forceinline__ uint64_t pack2(float lo, float hi) {
    uint64_t r; asm("mov.b64 %0,{%1,%2};" : "=l"(r) : "f"(lo), "f"(hi)); return r;
}
__device__ __forceinline__ float2 unpack2(uint64_t v) {
    float2 f; asm("mov.b64 {%0,%1},%2;" : "=f"(f.x), "=f"(f.y) : "l"(v)); return f;
}
__device__ __forceinline__ void ffma2(uint64_t& d, uint64_t a, uint64_t b) {
    asm("fma.rn.f32x2 %0, %1, %2, %0;" : "+l"(d) : "l"(a), "l"(b));
}

// ---------------- K0: detect edge dtype ----------------
__global__ void k_detect(const int* __restrict__ a, const int* __restrict__ b) {
    __shared__ int sa, sb;
    if (threadIdx.x == 0) { sa = 0; sb = 0; }
    __syncthreads();
    atomicOr(&sa, a[2 * threadIdx.x + 1]);
    atomicOr(&sb, b[2 * threadIdx.x + 1]);
    __syncthreads();
    if (threadIdx.x == 0) {
        g_is64_a = (sa == 0) ? 1 : 0;
        g_is64_b = (sb == 0) ? 1 : 0;
    }
}
__global__ void k_zero(int* __restrict__ deg, int n) {
    int i = blockIdx.x * blockDim.x + threadIdx.x;
    if (i < n) deg[i] = 0;
}

// ---------------- K1: h = x @ W1, double-buffered, f32x2 FMA, fused attn ----
#define KT 32
#define NSTEP ((C_IN + KT - 1) / KT)   // 10
__global__ void __launch_bounds__(256, 2)
k_gemm1(const float* __restrict__ x,
        const float* __restrict__ W1,
        const float* __restrict__ att_src,
        const float* __restrict__ att_dst, int N) {
    __shared__ float xs[2][KT][68];
    __shared__ float Ws[2][KT][64];
    const int tid = threadIdx.x;
    const int nb  = blockIdx.x * 64;
    const int n0  = (tid >> 4) * 4;
    const int c0  = (tid & 15) * 4;

    uint64_t acc[4][2];
#pragma unroll
    for (int i = 0; i < 4; i++) { acc[i][0] = pack2(0.f, 0.f); acc[i][1] = pack2(0.f, 0.f); }

    // stage loader: 64 nodes x KT cols of x (transposed) + KT x 64 of W1
#define LOAD_STAGE(s, buf)                                                 \
    do {                                                                   \
        int j0_ = (s) * KT;                                                \
        _Pragma("unroll")                                                  \
        for (int k = 0; k < (64 * KT) / 256; k++) {                        \
            int idx = tid + k * 256;                                       \
            int n_ = idx / KT, j_ = idx % KT;                              \
            int nn = nb + n_;                                              \
            float v = 0.f;                                                 \
            if ((j0_ + j_) < C_IN && nn < N)                               \
                v = x[(size_t)nn * C_IN + j0_ + j_];                       \
            xs[buf][j_][n_] = v;                                           \
        }                                                                  \
        _Pragma("unroll")                                                  \
        for (int k = 0; k < (64 * KT) / 256; k++) {                        \
            int idx = tid + k * 256;                                       \
            int j_ = idx >> 6, c_ = idx & 63;                              \
            float v = 0.f;                                                 \
            if ((j0_ + j_) < C_IN) v = W1[(size_t)(j0_ + j_) * 64 + c_];   \
            Ws[buf][j_][c_] = v;                                           \
        }                                                                  \
    } while (0)

    LOAD_STAGE(0, 0);
    __syncthreads();
    for (int s = 0; s < NSTEP; s++) {
        int cur = s & 1;
        if (s + 1 < NSTEP) LOAD_STAGE(s + 1, cur ^ 1);  // overlap with compute
#pragma unroll
        for (int j = 0; j < KT; j++) {
            float4 a = *(const float4*)&xs[cur][j][n0];
            ulonglong2 bb = *(const ulonglong2*)&Ws[cur][j][c0];  // one LDS.128
            uint64_t b0 = bb.x, b1 = bb.y;
            uint64_t ax = pack2(a.x, a.x), ay = pack2(a.y, a.y);
            uint64_t az = pack2(a.z, a.z), aw = pack2(a.w, a.w);
            ffma2(acc[0][0], ax, b0); ffma2(acc[0][1], ax, b1);
            ffma2(acc[1][0], ay, b0); ffma2(acc[1][1], ay, b1);
            ffma2(acc[2][0], az, b0); ffma2(acc[2][1], az, b1);
            ffma2(acc[3][0], aw, b0); ffma2(acc[3][1], aw, b1);
        }
        __syncthreads();
    }
#undef LOAD_STAGE

    // fused attention epilogue (exp-factorized form)
    float4 us = *(const float4*)&att_src[c0];
    float4 ud = *(const float4*)&att_dst[c0];
    int lane = tid & 31;
    int head = (lane & 15) >> 2;

    float pas[4], pad[4];
#pragma unroll
    for (int i = 0; i < 4; i++) {
        float2 lo = unpack2(acc[i][0]), hi = unpack2(acc[i][1]);
        int n = nb + n0 + i;
        if (n < N) {
            __half2 h2a = __floats2half2_rn(lo.x, lo.y);
            __half2 h2b = __floats2half2_rn(hi.x, hi.y);
            uint2 pk;
            pk.x = *(uint32_t*)&h2a;
            pk.y = *(uint32_t*)&h2b;
            *(uint2*)&g_hh[(size_t)n * C1 + c0] = pk;
        }
        pas[i] = lo.x * us.x + lo.y * us.y + hi.x * us.z + hi.y * us.w;
        pad[i] = lo.x * ud.x + lo.y * ud.y + hi.x * ud.z + hi.y * ud.w;
    }
#pragma unroll
    for (int off = 1; off <= 2; off <<= 1) {
#pragma unroll
        for (int i = 0; i < 4; i++) {
            pas[i] += __shfl_xor_sync(0xffffffffu, pas[i], off);
            pad[i] += __shfl_xor_sync(0xffffffffu, pad[i], off);
        }
    }
    if ((lane & 3) == 0) {
#pragma unroll
        for (int i = 0; i < 4; i++) {
            int n = nb + n0 + i;
            if (n < N) {
                g_eas[(size_t)n * 4 + head] =
                    make_float2(__expf(pas[i]), __expf(SLOPE * pas[i]));
                g_ad[(size_t)n * 4 + head] = pad[i];
            }
        }
    }
}

// ---------------- single-pass bucket CSR scatter ----------------
__global__ void k_scatter(const int* __restrict__ ei, long long E, const int* flag,
                          int* __restrict__ deg, int* __restrict__ csr) {
    long long e = (long long)blockIdx.x * blockDim.x + threadIdx.x;
    if (e >= E) return;
    int src, dst;
    if (*flag) {
        src = (int)((const long long*)ei)[e];
        dst = (int)((const long long*)ei)[E + e];
    } else {
        src = ei[(size_t)e];
        dst = ei[(size_t)(E + e)];
    }
    int pos = atomicAdd(&deg[dst], 1);
    if (pos < BUCKET) csr[((size_t)dst << 7) + pos] = src;
}

// ---------------- GAT gather: warp per dst, int4 CSR, exp-free edges ----------
__global__ void k_gat_gather(const float* __restrict__ b1, int N) {
    int n = (blockIdx.x * blockDim.x + threadIdx.x) >> 5;
    int lane = threadIdx.x & 31;
    if (n >= N) return;
    int head = lane >> 3;
    float adv = g_ad[n * 4 + head];
    float ead  = __expf(adv);
    float ea2d = __expf(SLOPE * adv);
    float th   = __expf(-adv);
    float2 es = g_eas[(size_t)n * 4 + head];
    float w = (es.x > th) ? es.x * ead : es.y * ea2d;
    float2 hv = __half22float2(*(const __half2*)&g_hh[(size_t)n * C1 + lane * 2]);
    float den = w;
    float ax = w * hv.x, ay = w * hv.y;
    size_t roff = (size_t)n << 7;
    int deg = g_dega[n];
    if (deg > BUCKET) deg = BUCKET;
    int j = 0;
    for (; j + 4 <= deg; j += 4) {
        int4 ss = *(const int4*)&g_csra[roff + j];
        float2 h0 = __half22float2(*(const __half2*)&g_hh[(size_t)ss.x * C1 + lane * 2]);
        float2 h1 = __half22float2(*(const __half2*)&g_hh[(size_t)ss.y * C1 + lane * 2]);
        float2 h2 = __half22float2(*(const __half2*)&g_hh[(size_t)ss.z * C1 + lane * 2]);
        float2 h3 = __half22float2(*(const __half2*)&g_hh[(size_t)ss.w * C1 + lane * 2]);
        float2 e0 = g_eas[(size_t)ss.x * 4 + head];
        float2 e1 = g_eas[(size_t)ss.y * 4 + head];
        float2 e2 = g_eas[(size_t)ss.z * 4 + head];
        float2 e3 = g_eas[(size_t)ss.w * 4 + head];
        float w0 = (e0.x > th) ? e0.x * ead : e0.y * ea2d;
        float w1 = (e1.x > th) ? e1.x * ead : e1.y * ea2d;
        float w2 = (e2.x > th) ? e2.x * ead : e2.y * ea2d;
        float w3 = (e3.x > th) ? e3.x * ead : e3.y * ea2d;
        den += (w0 + w1) + (w2 + w3);
        ax += w0 * h0.x + w1 * h1.x + w2 * h2.x + w3 * h3.x;
        ay += w0 * h0.y + w1 * h1.y + w2 * h2.y + w3 * h3.y;
    }
    for (; j < deg; j++) {
        int s0 = g_csra[roff + j];
        float2 e0 = g_eas[(size_t)s0 * 4 + head];
        float w0 = (e0.x > th) ? e0.x * ead : e0.y * ea2d;
        float2 h0 = __half22float2(*(const __half2*)&g_hh[(size_t)s0 * C1 + lane * 2]);
        den += w0;
        ax += w0 * h0.x;
        ay += w0 * h0.y;
    }
    float r = 1.f / den;
    float2 bv = *(const float2*)&b1[lane * 2];
    float2 o;
    o.x = fmaxf(ax * r + bv.x, 0.f);
    o.y = fmaxf(ay * r + bv.y, 0.f);
    *(float2*)&g_x1[(size_t)n * C1 + lane * 2] = o;
}

// ---------------- GCN prep: h2s = dinv*(x1 @ W2) fp16, dinv ----------
__global__ void k_gcn_prep(const float* __restrict__ W2, int N) {
    __shared__ float Wsh[C1 * OUT2];
    int tid = threadIdx.x;
    for (int i = tid; i < C1 * OUT2; i += blockDim.x) Wsh[i] = W2[i];
    __syncthreads();
    int warp = tid >> 5, lane = tid & 31;
    int n = blockIdx.x * (blockDim.x >> 5) + warp;
    if (n >= N) return;
    float dv = rsqrtf((float)(g_degb[n] + 1));
    if (lane == 0) g_dinv[n] = dv;
    float acc = 0.f;
#pragma unroll
    for (int k = 0; k < C1; k++)
        acc += g_x1[(size_t)n * C1 + k] * Wsh[k * OUT2 + lane];
    g_h2s[(size_t)n * OUT2 + lane] = __float2half_rn(acc * dv);
}

// ---------------- GCN gather: warp per dst, int4 CSR, 8-edge body ----------
__global__ void k_gcn_gather(const float* __restrict__ b2,
                             float* __restrict__ out, int N) {
    int n = (blockIdx.x * blockDim.x + threadIdx.x) >> 5;
    int lane = threadIdx.x & 31;
    if (n >= N) return;
    float dv = g_dinv[n];
    float acc = __half2float(g_h2s[(size_t)n * OUT2 + lane]);  // self term
    size_t roff = (size_t)n << 7;
    int deg = g_degb[n];
    if (deg > BUCKET) deg = BUCKET;
    int j = 0;
    for (; j + 8 <= deg; j += 8) {
        int4 sa = *(const int4*)&g_csrb[roff + j];
        int4 sb = *(const int4*)&g_csrb[roff + j + 4];
        float v0 = __half2float(g_h2s[(size_t)sa.x * OUT2 + lane]);
        float v1 = __half2float(g_h2s[(size_t)sa.y * OUT2 + lane]);
        float v2 = __half2float(g_h2s[(size_t)sa.z * OUT2 + lane]);
        float v3 = __half2float(g_h2s[(size_t)sa.w * OUT2 + lane]);
        float v4 = __half2float(g_h2s[(size_t)sb.x * OUT2 + lane]);
        float v5 = __half2float(g_h2s[(size_t)sb.y * OUT2 + lane]);
        float v6 = __half2float(g_h2s[(size_t)sb.z * OUT2 + lane]);
        float v7 = __half2float(g_h2s[(size_t)sb.w * OUT2 + lane]);
        acc += ((v0 + v1) + (v2 + v3)) + ((v4 + v5) + (v6 + v7));
    }
    for (; j + 4 <= deg; j += 4) {
        int4 sa = *(const int4*)&g_csrb[roff + j];
        acc += __half2float(g_h2s[(size_t)sa.x * OUT2 + lane])
             + __half2float(g_h2s[(size_t)sa.y * OUT2 + lane])
             + __half2float(g_h2s[(size_t)sa.z * OUT2 + lane])
             + __half2float(g_h2s[(size_t)sa.w * OUT2 + lane]);
    }
    for (; j < deg; j++) {
        int s0 = g_csrb[roff + j];
        acc += __half2float(g_h2s[(size_t)s0 * OUT2 + lane]);
    }
    out[(size_t)n * OUT2 + lane] = b2[lane] + dv * acc;
}

// ---------------- launch (forked-stream graph; static resources) ----------------
extern "C" void kernel_launch(void* const* d_in, const int* in_sizes, int n_in,
                              void* d_out, int out_size) {
    const float* x       = (const float*)d_in[0];
    const float* W1      = (const float*)d_in[1];
    const float* att_src = (const float*)d_in[2];
    const float* att_dst = (const float*)d_in[3];
    const float* b1      = (const float*)d_in[4];
    const float* W2      = (const float*)d_in[5];
    const float* b2      = (const float*)d_in[6];
    const int* ei        = (const int*)d_in[7];
    const int* sei       = (const int*)d_in[8];
    float* out = (float*)d_out;

    int N = in_sizes[0] / C_IN;
    long long E  = in_sizes[7] / 2;
    long long E2 = in_sizes[8] / 2;
    int nb = (N + 255) / 256;

    int *p_dega, *p_degb, *p_csra, *p_csrb, *p_fa, *p_fb;
    cudaGetSymbolAddress((void**)&p_dega, g_dega);
    cudaGetSymbolAddress((void**)&p_degb, g_degb);
    cudaGetSymbolAddress((void**)&p_csra, g_csra);
    cudaGetSymbolAddress((void**)&p_csrb, g_csrb);
    cudaGetSymbolAddress((void**)&p_fa, g_is64_a);
    cudaGetSymbolAddress((void**)&p_fb, g_is64_b);

    // created once on the correctness call; reused thereafter (no alloc in capture)
    static cudaStream_t s1 = nullptr, s2 = nullptr;
    static cudaEvent_t evF = nullptr, evA = nullptr, evB = nullptr;
    if (!s1) {
        cudaStreamCreateWithFlags(&s1, cudaStreamNonBlocking);
        cudaStreamCreateWithFlags(&s2, cudaStreamNonBlocking);
        cudaEventCreateWithFlags(&evF, cudaEventDisableTiming);
        cudaEventCreateWithFlags(&evA, cudaEventDisableTiming);
        cudaEventCreateWithFlags(&evB, cudaEventDisableTiming);
    }

    // detect on origin stream first (both CSR branches need the dtype flags)
    k_detect<<<1, 128>>>(ei, sei);
    cudaEventRecord(evF, 0);
    cudaStreamWaitEvent(s1, evF, 0);
    cudaStreamWaitEvent(s2, evF, 0);

    // branch S1: GAT bucket CSR (single pass)
    k_zero<<<nb, 256, 0, s1>>>(p_dega, N);
    k_scatter<<<(unsigned)((E + 255) / 256), 256, 0, s1>>>(ei, E, p_fa, p_dega, p_csra);
    cudaEventRecord(evA, s1);

    // branch S2: GCN bucket CSR (single pass)
    k_zero<<<nb, 256, 0, s2>>>(p_degb, N);
    k_scatter<<<(unsigned)((E2 + 255) / 256), 256, 0, s2>>>(sei, E2, p_fb, p_degb, p_csrb);
    cudaEventRecord(evB, s2);

    // origin stream: dense compute with fused attention
    k_gemm1<<<(N + 63) / 64, 256>>>(x, W1, att_src, att_dst, N);

    cudaStreamWaitEvent(0, evA, 0);
    k_gat_gather<<<(N * 32 + 255) / 256, 256>>>(b1, N);
    cudaStreamWaitEvent(0, evB, 0);
    k_gcn_prep<<<(N + 7) / 8, 256>>>(W2, N);
    k_gcn_gather<<<(N * 32 + 255) / 256, 256>>>(b2, out, N);
}

// round 17
// speedup vs baseline: 1.5044x; 1.0281x over previous
#include <cuda_runtime.h>
#include <cuda_fp16.h>
#include <cstdint>

#define NMAX   100352
#define BUCKET 128                 // per-node CSR capacity (Poisson(32) tail safe)
#define C_IN   300
#define C1     64
#define HEADS  4
#define OUT2   32
#define SLOPE  0.2f

// ---------------- device scratch ----------------
__device__ __align__(16) __half g_hh[(size_t)NMAX * C1];    // x@W1 fp16     [N,64]
__device__ __align__(16) float2 g_eas[(size_t)NMAX * HEADS];// (exp(as), exp(.2as))
__device__ __align__(16) float  g_ad[(size_t)NMAX * HEADS];
__device__ __align__(16) __half g_h2s[(size_t)NMAX * OUT2]; // dinv*(x1@W2)  [N,32] fp16
__device__ __align__(16) float  g_dinv[NMAX];
__device__ int g_dega[NMAX], g_degb[NMAX];
__device__ __align__(16) int g_csra[(size_t)NMAX * BUCKET];
__device__ __align__(16) int g_csrb[(size_t)NMAX * BUCKET];
__device__ int g_is64_a, g_is64_b;

__device__ __forceinline__ float leaky(float v) { return v > 0.f ? v : SLOPE * v; }

__device__ __forceinline__ uint64_t pack2(float lo, float hi) {
    uint64_t r; asm("mov.b64 %0,{%1,%2};" : "=l"(r) : "f"(lo), "f"(hi)); return r;
}
__device__ __forceinline__ float2 unpack2(uint64_t v) {
    float2 f; asm("mov.b64 {%0,%1},%2;" : "=f"(f.x), "=f"(f.y) : "l"(v)); return f;
}
__device__ __forceinline__ void ffma2(uint64_t& d, uint64_t a, uint64_t b) {
    asm("fma.rn.f32x2 %0, %1, %2, %0;" : "+l"(d) : "l"(a), "l"(b));
}

// ---------------- K0: detect edge dtype ----------------
__global__ void k_detect(const int* __restrict__ a, const int* __restrict__ b) {
    __shared__ int sa, sb;
    if (threadIdx.x == 0) { sa = 0; sb = 0; }
    __syncthreads();
    atomicOr(&sa, a[2 * threadIdx.x + 1]);
    atomicOr(&sb, b[2 * threadIdx.x + 1]);
    __syncthreads();
    if (threadIdx.x == 0) {
        g_is64_a = (sa == 0) ? 1 : 0;
        g_is64_b = (sb == 0) ? 1 : 0;
    }
}
__global__ void k_zero(int* __restrict__ deg, int n) {
    int i = blockIdx.x * blockDim.x + threadIdx.x;
    if (i < n) deg[i] = 0;
}

// ---------------- K1: h = x @ W1 (f32x2) + fused attn reduction (R14 best) ----
#define KT 64
__global__ void k_gemm1(const float* __restrict__ x,
                        const float* __restrict__ W1,
                        const float* __restrict__ att_src,
                        const float* __restrict__ att_dst, int N) {
    __shared__ float xs[KT][68];
    __shared__ float Ws[KT][64];
    const int tid = threadIdx.x;
    const int nb  = blockIdx.x * 64;
    const int n0  = (tid >> 4) * 4;
    const int c0  = (tid & 15) * 4;

    uint64_t acc[4][2];
#pragma unroll
    for (int i = 0; i < 4; i++) { acc[i][0] = pack2(0.f, 0.f); acc[i][1] = pack2(0.f, 0.f); }

    for (int j0 = 0; j0 < C_IN; j0 += KT) {
#pragma unroll
        for (int k = 0; k < (64 * KT) / 256; k++) {
            int idx = tid + k * 256;
            int n = idx / KT, j = idx % KT;
            int nn = nb + n;
            float v = 0.f;
            if ((j0 + j) < C_IN && nn < N) v = x[(size_t)nn * C_IN + j0 + j];
            xs[j][n] = v;
        }
#pragma unroll
        for (int k = 0; k < (64 * KT) / 256; k++) {
            int idx = tid + k * 256;
            int j = idx >> 6, c = idx & 63;
            float v = 0.f;
            if ((j0 + j) < C_IN) v = W1[(size_t)(j0 + j) * 64 + c];
            Ws[j][c] = v;
        }
        __syncthreads();
#pragma unroll
        for (int j = 0; j < KT; j++) {
            float4 a = *(const float4*)&xs[j][n0];
            uint64_t b0 = *(const uint64_t*)&Ws[j][c0];
            uint64_t b1 = *(const uint64_t*)&Ws[j][c0 + 2];
            uint64_t ax = pack2(a.x, a.x), ay = pack2(a.y, a.y);
            uint64_t az = pack2(a.z, a.z), aw = pack2(a.w, a.w);
            ffma2(acc[0][0], ax, b0); ffma2(acc[0][1], ax, b1);
            ffma2(acc[1][0], ay, b0); ffma2(acc[1][1], ay, b1);
            ffma2(acc[2][0], az, b0); ffma2(acc[2][1], az, b1);
            ffma2(acc[3][0], aw, b0); ffma2(acc[3][1], aw, b1);
        }
        __syncthreads();
    }

    float4 us = *(const float4*)&att_src[c0];
    float4 ud = *(const float4*)&att_dst[c0];
    int lane = tid & 31;
    int head = (lane & 15) >> 2;

    float pas[4], pad[4];
#pragma unroll
    for (int i = 0; i < 4; i++) {
        float2 lo = unpack2(acc[i][0]), hi = unpack2(acc[i][1]);
        int n = nb + n0 + i;
        if (n < N) {
            __half2 h2a = __floats2half2_rn(lo.x, lo.y);
            __half2 h2b = __floats2half2_rn(hi.x, hi.y);
            uint2 pk;
            pk.x = *(uint32_t*)&h2a;
            pk.y = *(uint32_t*)&h2b;
            *(uint2*)&g_hh[(size_t)n * C1 + c0] = pk;
        }
        pas[i] = lo.x * us.x + lo.y * us.y + hi.x * us.z + hi.y * us.w;
        pad[i] = lo.x * ud.x + lo.y * ud.y + hi.x * ud.z + hi.y * ud.w;
    }
#pragma unroll
    for (int off = 1; off <= 2; off <<= 1) {
#pragma unroll
        for (int i = 0; i < 4; i++) {
            pas[i] += __shfl_xor_sync(0xffffffffu, pas[i], off);
            pad[i] += __shfl_xor_sync(0xffffffffu, pad[i], off);
        }
    }
    if ((lane & 3) == 0) {
#pragma unroll
        for (int i = 0; i < 4; i++) {
            int n = nb + n0 + i;
            if (n < N) {
                g_eas[(size_t)n * 4 + head] =
                    make_float2(__expf(pas[i]), __expf(SLOPE * pas[i]));
                g_ad[(size_t)n * 4 + head] = pad[i];
            }
        }
    }
}

// ---------------- single-pass bucket CSR scatter ----------------
__global__ void k_scatter(const int* __restrict__ ei, long long E, const int* flag,
                          int* __restrict__ deg, int* __restrict__ csr) {
    long long e = (long long)blockIdx.x * blockDim.x + threadIdx.x;
    if (e >= E) return;
    int src, dst;
    if (*flag) {
        src = (int)((const long long*)ei)[e];
        dst = (int)((const long long*)ei)[E + e];
    } else {
        src = ei[(size_t)e];
        dst = ei[(size_t)(E + e)];
    }
    int pos = atomicAdd(&deg[dst], 1);
    if (pos < BUCKET) csr[((size_t)dst << 7) + pos] = src;
}

// ---------------- fused GAT gather + GCN prep ----------
// Phase A (per warp = dst node): softmax-weighted neighbor aggregation with
// factorized exp; x1 row (64 cols) ends in registers (float2 per lane).
// Phase B: h2s[n] = dinv * (relu(x1+b1) @ W2) via shuffle-broadcast GEMV
// against W2 staged in smem. Eliminates the separate gcn_prep kernel and the
// fp32 x1 round-trip through global memory.
__global__ void k_gat_fused(const float* __restrict__ b1,
                            const float* __restrict__ W2, int N) {
    __shared__ float Wsh[C1 * OUT2];   // 8 KB
    int tid = threadIdx.x;
    for (int i = tid; i < C1 * OUT2; i += blockDim.x) Wsh[i] = W2[i];
    __syncthreads();

    int n = (blockIdx.x * blockDim.x + tid) >> 5;
    int lane = tid & 31;
    if (n >= N) return;

    // ---- Phase A: GAT aggregation ----
    int head = lane >> 3;
    float adv = g_ad[n * 4 + head];
    float ead  = __expf(adv);
    float ea2d = __expf(SLOPE * adv);
    float th   = __expf(-adv);
    float2 es = g_eas[(size_t)n * 4 + head];
    float w = (es.x > th) ? es.x * ead : es.y * ea2d;   // self loop
    float2 hv = __half22float2(*(const __half2*)&g_hh[(size_t)n * C1 + lane * 2]);
    float den = w;
    float ax = w * hv.x, ay = w * hv.y;
    size_t roff = (size_t)n << 7;
    int deg = g_dega[n];
    if (deg > BUCKET) deg = BUCKET;
    int j = 0;
    for (; j + 4 <= deg; j += 4) {
        int4 ss = *(const int4*)&g_csra[roff + j];
        float2 h0 = __half22float2(*(const __half2*)&g_hh[(size_t)ss.x * C1 + lane * 2]);
        float2 h1 = __half22float2(*(const __half2*)&g_hh[(size_t)ss.y * C1 + lane * 2]);
        float2 h2 = __half22float2(*(const __half2*)&g_hh[(size_t)ss.z * C1 + lane * 2]);
        float2 h3 = __half22float2(*(const __half2*)&g_hh[(size_t)ss.w * C1 + lane * 2]);
        float2 e0 = g_eas[(size_t)ss.x * 4 + head];
        float2 e1 = g_eas[(size_t)ss.y * 4 + head];
        float2 e2 = g_eas[(size_t)ss.z * 4 + head];
        float2 e3 = g_eas[(size_t)ss.w * 4 + head];
        float w0 = (e0.x > th) ? e0.x * ead : e0.y * ea2d;
        float w1 = (e1.x > th) ? e1.x * ead : e1.y * ea2d;
        float w2 = (e2.x > th) ? e2.x * ead : e2.y * ea2d;
        float w3 = (e3.x > th) ? e3.x * ead : e3.y * ea2d;
        den += (w0 + w1) + (w2 + w3);
        ax += w0 * h0.x + w1 * h1.x + w2 * h2.x + w3 * h3.x;
        ay += w0 * h0.y + w1 * h1.y + w2 * h2.y + w3 * h3.y;
    }
    for (; j < deg; j++) {
        int s0 = g_csra[roff + j];
        float2 e0 = g_eas[(size_t)s0 * 4 + head];
        float w0 = (e0.x > th) ? e0.x * ead : e0.y * ea2d;
        float2 h0 = __half22float2(*(const __half2*)&g_hh[(size_t)s0 * C1 + lane * 2]);
        den += w0;
        ax += w0 * h0.x;
        ay += w0 * h0.y;
    }
    float r = 1.f / den;
    float2 bv = *(const float2*)&b1[lane * 2];
    float x1a = fmaxf(ax * r + bv.x, 0.f);   // x1[2*lane]
    float x1b = fmaxf(ay * r + bv.y, 0.f);   // x1[2*lane+1]

    // ---- Phase B: h2s = dinv * (x1 @ W2), x1 row held across warp ----
    float dv = rsqrtf((float)(g_degb[n] + 1));
    if (lane == 0) g_dinv[n] = dv;
    float acc2 = 0.f;
#pragma unroll
    for (int k = 0; k < 32; k++) {
        float xv0 = __shfl_sync(0xffffffffu, x1a, k);
        float xv1 = __shfl_sync(0xffffffffu, x1b, k);
        acc2 += xv0 * Wsh[(2 * k) * OUT2 + lane]
              + xv1 * Wsh[(2 * k + 1) * OUT2 + lane];
    }
    g_h2s[(size_t)n * OUT2 + lane] = __float2half_rn(acc2 * dv);
}

// ---------------- GCN gather: warp per dst, int4 CSR, 8-edge body ----------
__global__ void k_gcn_gather(const float* __restrict__ b2,
                             float* __restrict__ out, int N) {
    int n = (blockIdx.x * blockDim.x + threadIdx.x) >> 5;
    int lane = threadIdx.x & 31;
    if (n >= N) return;
    float dv = g_dinv[n];
    float acc = __half2float(g_h2s[(size_t)n * OUT2 + lane]);  // self term
    size_t roff = (size_t)n << 7;
    int deg = g_degb[n];
    if (deg > BUCKET) deg = BUCKET;
    int j = 0;
    for (; j + 8 <= deg; j += 8) {
        int4 sa = *(const int4*)&g_csrb[roff + j];
        int4 sb = *(const int4*)&g_csrb[roff + j + 4];
        float v0 = __half2float(g_h2s[(size_t)sa.x * OUT2 + lane]);
        float v1 = __half2float(g_h2s[(size_t)sa.y * OUT2 + lane]);
        float v2 = __half2float(g_h2s[(size_t)sa.z * OUT2 + lane]);
        float v3 = __half2float(g_h2s[(size_t)sa.w * OUT2 + lane]);
        float v4 = __half2float(g_h2s[(size_t)sb.x * OUT2 + lane]);
        float v5 = __half2float(g_h2s[(size_t)sb.y * OUT2 + lane]);
        float v6 = __half2float(g_h2s[(size_t)sb.z * OUT2 + lane]);
        float v7 = __half2float(g_h2s[(size_t)sb.w * OUT2 + lane]);
        acc += ((v0 + v1) + (v2 + v3)) + ((v4 + v5) + (v6 + v7));
    }
    for (; j + 4 <= deg; j += 4) {
        int4 sa = *(const int4*)&g_csrb[roff + j];
        acc += __half2float(g_h2s[(size_t)sa.x * OUT2 + lane])
             + __half2float(g_h2s[(size_t)sa.y * OUT2 + lane])
             + __half2float(g_h2s[(size_t)sa.z * OUT2 + lane])
             + __half2float(g_h2s[(size_t)sa.w * OUT2 + lane]);
    }
    for (; j < deg; j++) {
        int s0 = g_csrb[roff + j];
        acc += __half2float(g_h2s[(size_t)s0 * OUT2 + lane]);
    }
    out[(size_t)n * OUT2 + lane] = b2[lane] + dv * acc;
}

// ---------------- launch (forked-stream graph; static resources) ----------------
extern "C" void kernel_launch(void* const* d_in, const int* in_sizes, int n_in,
                              void* d_out, int out_size) {
    const float* x       = (const float*)d_in[0];
    const float* W1      = (const float*)d_in[1];
    const float* att_src = (const float*)d_in[2];
    const float* att_dst = (const float*)d_in[3];
    const float* b1      = (const float*)d_in[4];
    const float* W2      = (const float*)d_in[5];
    const float* b2      = (const float*)d_in[6];
    const int* ei        = (const int*)d_in[7];
    const int* sei       = (const int*)d_in[8];
    float* out = (float*)d_out;

    int N = in_sizes[0] / C_IN;
    long long E  = in_sizes[7] / 2;
    long long E2 = in_sizes[8] / 2;
    int nb = (N + 255) / 256;

    int *p_dega, *p_degb, *p_csra, *p_csrb, *p_fa, *p_fb;
    cudaGetSymbolAddress((void**)&p_dega, g_dega);
    cudaGetSymbolAddress((void**)&p_degb, g_degb);
    cudaGetSymbolAddress((void**)&p_csra, g_csra);
    cudaGetSymbolAddress((void**)&p_csrb, g_csrb);
    cudaGetSymbolAddress((void**)&p_fa, g_is64_a);
    cudaGetSymbolAddress((void**)&p_fb, g_is64_b);

    // created once on the correctness call; reused thereafter (no alloc in capture)
    static cudaStream_t s1 = nullptr, s2 = nullptr;
    static cudaEvent_t evF = nullptr, evA = nullptr, evB = nullptr;
    if (!s1) {
        cudaStreamCreateWithFlags(&s1, cudaStreamNonBlocking);
        cudaStreamCreateWithFlags(&s2, cudaStreamNonBlocking);
        cudaEventCreateWithFlags(&evF, cudaEventDisableTiming);
        cudaEventCreateWithFlags(&evA, cudaEventDisableTiming);
        cudaEventCreateWithFlags(&evB, cudaEventDisableTiming);
    }

    // detect on origin stream first (both CSR branches need the dtype flags)
    k_detect<<<1, 128>>>(ei, sei);
    cudaEventRecord(evF, 0);
    cudaStreamWaitEvent(s1, evF, 0);
    cudaStreamWaitEvent(s2, evF, 0);

    // branch S1: GAT bucket CSR (single pass)
    k_zero<<<nb, 256, 0, s1>>>(p_dega, N);
    k_scatter<<<(unsigned)((E + 255) / 256), 256, 0, s1>>>(ei, E, p_fa, p_dega, p_csra);
    cudaEventRecord(evA, s1);

    // branch S2: GCN bucket CSR (single pass)
    k_zero<<<nb, 256, 0, s2>>>(p_degb, N);
    k_scatter<<<(unsigned)((E2 + 255) / 256), 256, 0, s2>>>(sei, E2, p_fb, p_degb, p_csrb);
    cudaEventRecord(evB, s2);

    // origin stream: dense compute with fused attention
    k_gemm1<<<(N + 63) / 64, 256>>>(x, W1, att_src, att_dst, N);

    // fused GAT gather + GCN prep needs both CSR builds (deg_b for dinv)
    cudaStreamWaitEvent(0, evA, 0);
    cudaStreamWaitEvent(0, evB, 0);
    k_gat_fused<<<(N * 32 + 255) / 256, 256>>>(b1, W2, N);
    k_gcn_gather<<<(N * 32 + 255) / 256, 256>>>(b2, out, N);
}